// round 13
// baseline (speedup 1.0000x reference)
#include <cuda_runtime.h>
#include <cstdint>

// B=32, N=64, D=512
// score[b,i,j] = (dot(s_e[b,i,j,:], W) + bias) * adj[b,i,j], adj[b,0,1]=adj[b,1,0]=0
// Only i in {0,1} consumed. Outputs (float32, flattened tuple order):
//   final_id (32,2)=64 | s_e_score (32,2,64)=4096 | flag (32)=32

#define NB 32
#define NN 64
#define ND 512
#define GRID 128    // one block per half-row: 32 dots, single (b,i)
#define TPB  1024   // 32 warps, ONE dot per warp

// Per-row packed argmax slots + per-batch arrival counters (4 blocks/batch).
// The 4th arriver decodes, writes outputs, and resets -> deterministic replays.
__device__ unsigned long long g_slot[NB * 2] = {};
__device__ int g_cnt[NB] = {};

__global__ void __launch_bounds__(TPB, 1)
fused_kernel(const float* __restrict__ s_e,
             const float* __restrict__ adj,
             const float* __restrict__ W,
             const float* __restrict__ bias,
             float* __restrict__ out_id,
             float* __restrict__ out_score,
             float* __restrict__ out_flag) {
    int warp = threadIdx.x >> 5;
    int lane = threadIdx.x & 31;

    int p = blockIdx.x * 32 + warp;      // 0..4095 == (b*2+i)*64 + j
    int b = p >> 7;
    int i = (p >> 6) & 1;
    int j = p & 63;
    int row = p >> 6;                    // b*2 + i
    int j_base = blockIdx.x & 1 ? 32 : 0; // this block's j range start
    // (p0 = blockIdx.x*32 -> j_base = p0 & 63; blockIdx parity gives 0/32)

    __shared__ float s_sc[32];

    // ---------- one dot product per warp: 4 + 4 vector loads ----------
    const float4* base =
        (const float4*)(s_e + ((size_t)((b * NN + i) * NN + j)) * ND);
    const float4* wv = (const float4*)W;

    float adj_v = 0.f;
    if (lane == 0) {
        adj_v = adj[(b * NN + i) * NN + j];
        if ((i == 0 && j == 1) || (i == 1 && j == 0)) adj_v = 0.f;
    }
    float bias0 = __ldg(bias);

    float4 a0 = base[lane];
    float4 a1 = base[32 + lane];
    float4 a2 = base[64 + lane];
    float4 a3 = base[96 + lane];
    float4 w0 = wv[lane];
    float4 w1 = wv[32 + lane];
    float4 w2 = wv[64 + lane];
    float4 w3 = wv[96 + lane];

    float s = a0.x * w0.x + a0.y * w0.y + a0.z * w0.z + a0.w * w0.w
            + a1.x * w1.x + a1.y * w1.y + a1.z * w1.z + a1.w * w1.w
            + a2.x * w2.x + a2.y * w2.y + a2.z * w2.z + a2.w * w2.w
            + a3.x * w3.x + a3.y * w3.y + a3.z * w3.z + a3.w * w3.w;
#pragma unroll
    for (int off = 16; off; off >>= 1)
        s += __shfl_xor_sync(0xffffffffu, s, off);

    if (lane == 0) {
        float sc = (s + bias0) * adj_v;
        out_score[p] = sc;
        s_sc[warp] = sc;
    }
    __syncthreads();

    // ---------- warp 0: partial argmax over this block's 32 scores ----------
    if (warp == 0) {
        float v = s_sc[lane];
        int idx = lane;
#pragma unroll
        for (int off = 16; off; off >>= 1) {
            float ov = __shfl_xor_sync(0xffffffffu, v, off);
            int   oi = __shfl_xor_sync(0xffffffffu, idx, off);
            if (ov > v || (ov == v && oi < idx)) { v = ov; idx = oi; }
        }
        if (lane == 0) {
            int jg = j_base + idx;
            // Monotone float encoding; smaller j wins ties via (63 - jg).
            float c = v + 0.0f;                        // -0 -> +0
            unsigned int bits = __float_as_uint(c);
            unsigned int ord = (bits & 0x80000000u) ? ~bits : (bits | 0x80000000u);
            unsigned long long key =
                ((unsigned long long)ord << 32) | (unsigned long long)(63 - jg);
            atomicMax(&g_slot[row], key);
            __threadfence();
            int prev = atomicAdd(&g_cnt[b], 1);
            if (prev == 3) {                           // all 4 half-rows done
                __threadfence();
                unsigned long long k0 = atomicMax(&g_slot[b * 2], 0ULL);
                unsigned long long k1 = atomicMax(&g_slot[b * 2 + 1], 0ULL);
                int sub = 63 - (int)(k0 & 0xFFFFFFFFu);
                int obj = 63 - (int)(k1 & 0xFFFFFFFFu);
                out_id[b * 2]     = (float)sub;
                out_id[b * 2 + 1] = (float)obj;
                float f = 0.f;
                if (sub > 0 && obj > 0)      f = 3.f;
                else if (sub > 0)            f = 1.f;
                else if (obj > 0)            f = 2.f;
                out_flag[b] = f;
                g_slot[b * 2]     = 0ULL;              // reset for next replay
                g_slot[b * 2 + 1] = 0ULL;
                g_cnt[b]          = 0;
            }
        }
    }
}

extern "C" void kernel_launch(void* const* d_in, const int* in_sizes, int n_in,
                              void* d_out, int out_size) {
    const float* s_e  = (const float*)d_in[0];
    const float* adj  = (const float*)d_in[1];
    const float* W    = (const float*)d_in[2];
    const float* bias = (const float*)d_in[3];

    float* out       = (float*)d_out;
    float* out_id    = out;             // 64
    float* out_score = out + 64;        // 4096
    float* out_flag  = out + 64 + 4096; // 32

    fused_kernel<<<GRID, TPB>>>(s_e, adj, W, bias, out_id, out_score, out_flag);
}

// round 14
// speedup vs baseline: 1.0332x; 1.0332x over previous
#include <cuda_runtime.h>
#include <cstdint>

// B=32, N=64, D=512
// score[b,i,j] = (dot(s_e[b,i,j,:], W) + bias) * adj[b,i,j], adj[b,0,1]=adj[b,1,0]=0
// Only i in {0,1} consumed. adj is 0/1 -> skip the 2KB s_e row read when adj==0.
// Outputs (float32, flattened tuple order):
//   final_id (32,2)=64 | s_e_score (32,2,64)=4096 | flag (32)=32

#define NB 32
#define NN 64
#define ND 512
#define GRID 64     // one block per output row (b*2+i)
#define TPB  1024   // 32 warps x 2 dots = the row's 64 dot products

__device__ int g_pair[NB] = {};   // per-batch arrival counter (reset by consumer)
__device__ int g_ids[NB * 2];     // int mirror of final_id (overwritten each launch)

__global__ void __launch_bounds__(TPB, 1)
fused_kernel(const float* __restrict__ s_e,
             const float* __restrict__ adj,
             const float* __restrict__ W,
             const float* __restrict__ bias,
             float* __restrict__ out_id,
             float* __restrict__ out_score,
             float* __restrict__ out_flag) {
    int warp = threadIdx.x >> 5;
    int lane = threadIdx.x & 31;

    int row = blockIdx.x;            // 0..63 == b*2 + i
    int b   = row >> 1;
    int i   = row & 1;
    int j0  = warp * 2;              // this warp's two j's: j0, j0+1

    __shared__ float s_score[NN];

    // ---- Load adj first (tiny), W + bias concurrently (independent) ----
    float adj_mine = 0.f;
    if (lane < 2)
        adj_mine = adj[(b * NN + i) * NN + j0 + lane];
    float bias0 = __ldg(bias);
    const float4* wv = (const float4*)W;
    float4 w0 = wv[lane];
    float4 w1 = wv[32 + lane];
    float4 w2 = wv[64 + lane];
    float4 w3 = wv[96 + lane];

    float adj0 = __shfl_sync(0xffffffffu, adj_mine, 0);
    float adj1 = __shfl_sync(0xffffffffu, adj_mine, 1);
    if (j0 == 0) {                   // forced zeros at (0,1)/(1,0)
        if (i == 0) adj1 = 0.f;      // j = 1
        else        adj0 = 0.f;      // j = 0
    }

    // ---- Conditionally stream the two s_e rows (skip when adj == 0) ----
    const float4* base0 =
        (const float4*)(s_e + ((size_t)((b * NN + i) * NN + j0)) * ND);
    const float4* base1 = base0 + (ND / 4);      // j0+1 (contiguous)

    float s0 = 0.f, s1 = 0.f;
    if (adj0 != 0.f) {
        float4 a0 = base0[lane];
        float4 a1 = base0[32 + lane];
        float4 a2 = base0[64 + lane];
        float4 a3 = base0[96 + lane];
        s0 = a0.x * w0.x + a0.y * w0.y + a0.z * w0.z + a0.w * w0.w
           + a1.x * w1.x + a1.y * w1.y + a1.z * w1.z + a1.w * w1.w
           + a2.x * w2.x + a2.y * w2.y + a2.z * w2.z + a2.w * w2.w
           + a3.x * w3.x + a3.y * w3.y + a3.z * w3.z + a3.w * w3.w;
    }
    if (adj1 != 0.f) {
        float4 c0 = base1[lane];
        float4 c1 = base1[32 + lane];
        float4 c2 = base1[64 + lane];
        float4 c3 = base1[96 + lane];
        s1 = c0.x * w0.x + c0.y * w0.y + c0.z * w0.z + c0.w * w0.w
           + c1.x * w1.x + c1.y * w1.y + c1.z * w1.z + c1.w * w1.w
           + c2.x * w2.x + c2.y * w2.y + c2.z * w2.z + c2.w * w2.w
           + c3.x * w3.x + c3.y * w3.y + c3.z * w3.z + c3.w * w3.w;
    }

#pragma unroll
    for (int off = 16; off; off >>= 1) {
        s0 += __shfl_xor_sync(0xffffffffu, s0, off);
        s1 += __shfl_xor_sync(0xffffffffu, s1, off);
    }

    if (lane == 0) {
        float sc0 = (s0 + bias0) * adj0;   // adj==0 -> exact 0
        float sc1 = (s1 + bias0) * adj1;
        *(float2*)(out_score + row * NN + j0) = make_float2(sc0, sc1);
        s_score[j0]     = sc0;
        s_score[j0 + 1] = sc1;
    }
    __syncthreads();

    // ---------- warp 0: row argmax from SMEM ----------
    if (warp == 0) {
        float v0 = s_score[lane];
        float v1 = s_score[lane + 32];
        float v; int idx;
        if (v1 > v0) { v = v1; idx = lane + 32; }
        else         { v = v0; idx = lane; }
#pragma unroll
        for (int off = 16; off; off >>= 1) {
            float ov = __shfl_xor_sync(0xffffffffu, v, off);
            int   oi = __shfl_xor_sync(0xffffffffu, idx, off);
            if (ov > v || (ov == v && oi < idx)) { v = ov; idx = oi; }
        }
        if (lane == 0) {
            out_id[row] = (float)idx;
            g_ids[row]  = idx;
            __threadfence();                     // publish before pairing
            int prev = atomicAdd(&g_pair[b], 1);
            if (prev == 1) {                     // partner row already done
                __threadfence();                 // acquire partner's write
                int other = g_ids[row ^ 1];
                int sub = (i == 0) ? idx   : other;
                int obj = (i == 0) ? other : idx;
                float f = 0.f;
                if (sub > 0 && obj > 0)      f = 3.f;
                else if (sub > 0)            f = 1.f;
                else if (obj > 0)            f = 2.f;
                out_flag[b] = f;
                g_pair[b] = 0;                   // reset for next replay
            }
        }
    }
}

extern "C" void kernel_launch(void* const* d_in, const int* in_sizes, int n_in,
                              void* d_out, int out_size) {
    const float* s_e  = (const float*)d_in[0];
    const float* adj  = (const float*)d_in[1];
    const float* W    = (const float*)d_in[2];
    const float* bias = (const float*)d_in[3];

    float* out       = (float*)d_out;
    float* out_id    = out;             // 64
    float* out_score = out + 64;        // 4096
    float* out_flag  = out + 64 + 4096; // 32

    fused_kernel<<<GRID, TPB>>>(s_e, adj, W, bias, out_id, out_score, out_flag);
}